// round 3
// baseline (speedup 1.0000x reference)
#include <cuda_runtime.h>
#include <cstddef>

#define BB   16
#define NN   8192
#define SS   1024        // NPOINT
#define KK   32          // NSAMPLE
#define DD   9
#define MCOL (BB*SS*KK)  // 524288 columns
#define NBLK (MCOL/64)   // 8192 gemm blocks

// ---------------- device scratch (static: no cudaMalloc allowed) ----------------
__device__ float  g_X0[(size_t)DD  * MCOL];   // gathered input   (9  x 524288)
__device__ float  g_Y0[(size_t)64  * MCOL];   // layer0 raw out
__device__ float  g_Y1[(size_t)64  * MCOL];   // layer1 raw out
__device__ float  g_Y2[(size_t)128 * MCOL];   // layer2 raw out
__device__ int    g_cent[BB * SS];
__device__ double g_ps [(size_t)128 * NBLK];  // per-block channel sums
__device__ double g_pss[(size_t)128 * NBLK];  // per-block channel sumsq
__device__ float  g_scl[3][128];
__device__ float  g_shf[3][128];

// ---------------- FPS: one block per batch, sequential argmax loop ----------------
// distance formula matches XLA/NVPTX fp-contract=fast:
//   d = fma(dz,dz, fma(dy,dy, dx*dx))   (reduce-from-0 fma chain)
__global__ __launch_bounds__(1024) void fps_kernel(const float* __restrict__ xyz)
{
    extern __shared__ float sh[];
    float* sx = sh;
    float* sy = sh + NN;
    float* sz = sh + 2 * NN;
    __shared__ float rv[32];
    __shared__ int   ri[32];
    __shared__ int   s_far;

    int b = blockIdx.x, t = threadIdx.x;
    const float* xb = xyz + (size_t)b * NN * 3;
    for (int i = t; i < NN; i += 1024) {
        sx[i] = xb[i * 3 + 0];
        sy[i] = xb[i * 3 + 1];
        sz[i] = xb[i * 3 + 2];
    }
    float dist[8];
#pragma unroll
    for (int j = 0; j < 8; j++) dist[j] = 1e10f;
    if (t == 0) g_cent[b * SS] = 0;
    int far = 0;
    __syncthreads();

    for (int it = 1; it < SS; ++it) {
        float cx = sx[far], cy = sy[far], cz = sz[far];
        float bv = -1.0f; int bi = 0;
#pragma unroll
        for (int j = 0; j < 8; j++) {
            int p = j * 1024 + t;
            float dx = __fsub_rn(sx[p], cx);
            float dy = __fsub_rn(sy[p], cy);
            float dz = __fsub_rn(sz[p], cz);
            float d  = fmaf(dz, dz, fmaf(dy, dy, __fmul_rn(dx, dx)));
            float nd = fminf(dist[j], d);
            dist[j] = nd;
            if (nd > bv) { bv = nd; bi = p; }   // p increasing -> first-index tie rule
        }
        // warp argmax (tie -> smaller index)
#pragma unroll
        for (int o = 16; o > 0; o >>= 1) {
            float ov = __shfl_down_sync(0xffffffffu, bv, o);
            int   oi = __shfl_down_sync(0xffffffffu, bi, o);
            if (ov > bv || (ov == bv && oi < bi)) { bv = ov; bi = oi; }
        }
        int w = t >> 5, lane = t & 31;
        if (lane == 0) { rv[w] = bv; ri[w] = bi; }
        __syncthreads();
        if (w == 0) {
            bv = rv[lane]; bi = ri[lane];
#pragma unroll
            for (int o = 16; o > 0; o >>= 1) {
                float ov = __shfl_down_sync(0xffffffffu, bv, o);
                int   oi = __shfl_down_sync(0xffffffffu, bi, o);
                if (ov > bv || (ov == bv && oi < bi)) { bv = ov; bi = oi; }
            }
            if (lane == 0) { s_far = bi; g_cent[b * SS + it] = bi; }
        }
        __syncthreads();
        far = s_far;
    }
}

// ---------------- Ball query: thread-per-centroid streaming top-32 + gather ----------------
// sqr = (cn2 + pn2) - 2*dot, with norms/dot as ascending fma chains (matches XLA/cuBLAS)
__global__ __launch_bounds__(256) void ballquery_kernel(const float* __restrict__ xyz,
                                                        const float* __restrict__ points,
                                                        float* __restrict__ out_newxyz)
{
    __shared__ float4 sp[2048];
    int b = blockIdx.x >> 2;
    int s = ((blockIdx.x & 3) << 8) + threadIdx.x;

    int cidx = g_cent[b * SS + s];
    const float* cp = xyz + ((size_t)b * NN + cidx) * 3;
    float cx = cp[0], cy = cp[1], cz = cp[2];
    float cn2 = fmaf(cz, cz, fmaf(cy, cy, __fmul_rn(cx, cx)));

    out_newxyz[(b * SS + s) * 3 + 0] = cx;
    out_newxyz[(b * SS + s) * 3 + 1] = cy;
    out_newxyz[(b * SS + s) * 3 + 2] = cz;

    float dl[KK]; int il[KK];
#pragma unroll
    for (int k = 0; k < KK; k++) { dl[k] = 3.4e38f; il[k] = 0; }
    float dmax = 3.4e38f;

    for (int tile = 0; tile < 4; ++tile) {
        __syncthreads();
        for (int i = threadIdx.x; i < 2048; i += 256) {
            int gp = tile * 2048 + i;
            const float* pp = xyz + ((size_t)b * NN + gp) * 3;
            float px = pp[0], py = pp[1], pz = pp[2];
            float pn2 = fmaf(pz, pz, fmaf(py, py, __fmul_rn(px, px)));
            sp[i] = make_float4(px, py, pz, pn2);
        }
        __syncthreads();
        for (int i = 0; i < 2048; ++i) {
            float4 p = sp[i];
            float dot = fmaf(cz, p.z, fmaf(cy, p.y, __fmul_rn(cx, p.x)));
            float d   = __fsub_rn(__fadd_rn(cn2, p.w), __fmul_rn(2.0f, dot));
            if (d < dmax) {       // strict < : matches lax.top_k tie rule at boundary
                int gi = tile * 2048 + i;
                int j = KK - 1;
                while (j > 0 && dl[j - 1] > d) {   // insert after equals -> stable
                    dl[j] = dl[j - 1]; il[j] = il[j - 1]; --j;
                }
                dl[j] = d; il[j] = gi;
                dmax = dl[KK - 1];
            }
        }
    }

    // radius replacement + fused gather of the 9 input channels
    int first = il[0];
    int m0 = (b * SS + s) * KK;
    const float R2 = 0.04f;   // float32 of radius**2, matching weak-type cast
    for (int k = 0; k < KK; k++) {
        int gi = (dl[k] > R2) ? first : il[k];
        const float* pr = points + ((size_t)b * NN + gi) * DD;
#pragma unroll
        for (int c = 0; c < DD; c++)
            g_X0[(size_t)c * MCOL + m0 + k] = pr[c];
    }
}

// ---------------- GEMM + bias + deterministic BN partial stats ----------------
// block = 256 threads, tile = COUT rows x 64 cols. thread tile = R rows x 4 cols.
template<int CIN, int COUT, int LAYER>
__global__ __launch_bounds__(256) void gemm_kernel(const float* __restrict__ X,
                                                   float* __restrict__ Y,
                                                   const float* __restrict__ W,
                                                   const float* __restrict__ Bv)
{
    constexpr int R = COUT / 16;
    extern __shared__ float sm[];
    float* WsT  = sm;                    // [CIN][COUT] transposed weights
    float* Xs   = WsT + CIN * COUT;      // [CIN][64]
    float* ssum = Xs  + CIN * 64;        // [COUT]
    float* sss  = ssum + COUT;           // [COUT]

    int t = threadIdx.x;
    int col0 = blockIdx.x * 64;

    for (int i = t; i < CIN * COUT; i += 256) {
        int k = i / COUT, r = i - k * COUT;
        WsT[i] = W[r * CIN + k];
    }
    for (int i = t; i < CIN * 64; i += 256) {
        int c = i >> 6, x = i & 63;
        float v = X[(size_t)c * MCOL + col0 + x];
        if (LAYER > 0) v = fmaxf(fmaf(g_scl[LAYER - 1][c], v, g_shf[LAYER - 1][c]), 0.0f);
        Xs[i] = v;
    }
    __syncthreads();

    int cg = t & 15, rg = t >> 4;
    float acc[R][4];
#pragma unroll
    for (int r = 0; r < R; r++)
#pragma unroll
        for (int c = 0; c < 4; c++) acc[r][c] = 0.0f;

    const float4* Xs4 = reinterpret_cast<const float4*>(Xs);
    const float4* Ws4 = reinterpret_cast<const float4*>(WsT);
#pragma unroll
    for (int k = 0; k < CIN; k++) {
        float4 xv = Xs4[k * 16 + cg];
        float xa[4] = {xv.x, xv.y, xv.z, xv.w};
#pragma unroll
        for (int rr = 0; rr < R; rr += 4) {
            float4 wv = Ws4[k * (COUT / 4) + (rg * R + rr) / 4];
            float wa[4] = {wv.x, wv.y, wv.z, wv.w};
#pragma unroll
            for (int q = 0; q < 4; q++)
#pragma unroll
                for (int cc = 0; cc < 4; cc++)
                    acc[rr + q][cc] = fmaf(wa[q], xa[cc], acc[rr + q][cc]);
        }
    }

    int lane = t & 31;
#pragma unroll
    for (int rr = 0; rr < R; rr++) {
        int r = rg * R + rr;
        float bb = Bv[r];
        float y0 = acc[rr][0] + bb, y1 = acc[rr][1] + bb;
        float y2 = acc[rr][2] + bb, y3 = acc[rr][3] + bb;
        *reinterpret_cast<float4*>(Y + (size_t)r * MCOL + col0 + cg * 4) =
            make_float4(y0, y1, y2, y3);
        float ps = y0 + y1 + y2 + y3;
        float pq = y0*y0 + y1*y1 + y2*y2 + y3*y3;
#pragma unroll
        for (int o = 8; o > 0; o >>= 1) {
            ps += __shfl_xor_sync(0xffffffffu, ps, o);
            pq += __shfl_xor_sync(0xffffffffu, pq, o);
        }
        if ((lane & 15) == 0) { ssum[r] = ps; sss[r] = pq; }  // unique writer per row
    }
    __syncthreads();
    if (t < COUT) {
        g_ps [(size_t)t * NBLK + blockIdx.x] = (double)ssum[t];
        g_pss[(size_t)t * NBLK + blockIdx.x] = (double)sss[t];
    }
}

// ---------------- BN finalize: one block per channel, deterministic tree sum ----------------
__global__ __launch_bounds__(128) void finalize_kernel(const float* __restrict__ gamma,
                                                       const float* __restrict__ beta,
                                                       int layer)
{
    int c = blockIdx.x, t = threadIdx.x;
    __shared__ double sh1[128], sh2[128];
    double a = 0.0, q = 0.0;
    for (int i = t; i < NBLK; i += 128) {
        a += g_ps [(size_t)c * NBLK + i];
        q += g_pss[(size_t)c * NBLK + i];
    }
    sh1[t] = a; sh2[t] = q;
    __syncthreads();
    for (int o = 64; o > 0; o >>= 1) {
        if (t < o) { sh1[t] += sh1[t + o]; sh2[t] += sh2[t + o]; }
        __syncthreads();
    }
    if (t == 0) {
        double n = (double)MCOL;
        double mean = sh1[0] / n;
        double var  = sh2[0] / n - mean * mean;
        float sc = gamma[c] * rsqrtf((float)var + 1e-5f);
        g_scl[layer][c] = sc;
        g_shf[layer][c] = beta[c] - (float)mean * sc;
    }
}

// ---------------- final affine + relu + max over nsample, transposed write ----------------
__global__ __launch_bounds__(256) void maxpool_kernel(float* __restrict__ out)
{
    int g = blockIdx.x * 256 + threadIdx.x;   // (b,s,c) with c fastest
    int c = g & 127;
    int ms = g >> 7;                          // b*1024 + s
    float sc = g_scl[2][c], sh = g_shf[2][c];
    const float4* p = reinterpret_cast<const float4*>(g_Y2 + (size_t)c * MCOL + (size_t)ms * KK);
    float mx = -3.4e38f;
#pragma unroll
    for (int q = 0; q < 8; q++) {
        float4 v = p[q];
        mx = fmaxf(mx, fmaf(sc, v.x, sh));
        mx = fmaxf(mx, fmaf(sc, v.y, sh));
        mx = fmaxf(mx, fmaf(sc, v.z, sh));
        mx = fmaxf(mx, fmaf(sc, v.w, sh));
    }
    out[g] = fmaxf(mx, 0.0f);   // relu commutes with max
}

// ---------------- launch ----------------
extern "C" void kernel_launch(void* const* d_in, const int* in_sizes, int n_in,
                              void* d_out, int out_size)
{
    const float* xyz    = (const float*)d_in[0];
    const float* points = (const float*)d_in[1];
    const float* W0 = (const float*)d_in[2];
    const float* b0 = (const float*)d_in[3];
    const float* g0 = (const float*)d_in[4];
    const float* be0 = (const float*)d_in[5];
    const float* W1 = (const float*)d_in[6];
    const float* b1 = (const float*)d_in[7];
    const float* g1 = (const float*)d_in[8];
    const float* be1 = (const float*)d_in[9];
    const float* W2 = (const float*)d_in[10];
    const float* b2 = (const float*)d_in[11];
    const float* g2 = (const float*)d_in[12];
    const float* be2 = (const float*)d_in[13];

    float* out      = (float*)d_out;
    float* out_feat = out + BB * SS * 3;

    float *pX0, *pY0, *pY1, *pY2;
    cudaGetSymbolAddress((void**)&pX0, g_X0);
    cudaGetSymbolAddress((void**)&pY0, g_Y0);
    cudaGetSymbolAddress((void**)&pY1, g_Y1);
    cudaGetSymbolAddress((void**)&pY2, g_Y2);

    // FPS (96KB dynamic smem)
    cudaFuncSetAttribute(fps_kernel, cudaFuncAttributeMaxDynamicSharedMemorySize, 3 * NN * 4);
    fps_kernel<<<BB, 1024, 3 * NN * 4>>>(xyz);

    // ball query + gather + new_xyz output
    ballquery_kernel<<<BB * 4, 256>>>(xyz, points, out);

    // layer 0: 9 -> 64
    {
        size_t smem = (size_t)(9 * 64 + 9 * 64 + 2 * 64) * 4;
        cudaFuncSetAttribute(gemm_kernel<9, 64, 0>, cudaFuncAttributeMaxDynamicSharedMemorySize, (int)smem);
        gemm_kernel<9, 64, 0><<<NBLK, 256, smem>>>(pX0, pY0, W0, b0);
        finalize_kernel<<<64, 128>>>(g0, be0, 0);
    }
    // layer 1: 64 -> 64 (applies BN0+relu on input)
    {
        size_t smem = (size_t)(64 * 64 + 64 * 64 + 2 * 64) * 4;
        cudaFuncSetAttribute(gemm_kernel<64, 64, 1>, cudaFuncAttributeMaxDynamicSharedMemorySize, (int)smem);
        gemm_kernel<64, 64, 1><<<NBLK, 256, smem>>>(pY0, pY1, W1, b1);
        finalize_kernel<<<64, 128>>>(g1, be1, 1);
    }
    // layer 2: 64 -> 128 (applies BN1+relu on input)
    {
        size_t smem = (size_t)(64 * 128 + 64 * 64 + 2 * 128) * 4;
        cudaFuncSetAttribute(gemm_kernel<64, 128, 2>, cudaFuncAttributeMaxDynamicSharedMemorySize, (int)smem);
        gemm_kernel<64, 128, 2><<<NBLK, 256, smem>>>(pY1, pY2, W2, b2);
        finalize_kernel<<<128, 128>>>(g2, be2, 2);
    }
    // BN2 + relu + max over nsample -> transposed feature output
    maxpool_kernel<<<(BB * SS * 128) / 256, 256>>>(out_feat);
}

// round 4
// speedup vs baseline: 10.7612x; 10.7612x over previous
#include <cuda_runtime.h>
#include <cstddef>

#define BB   16
#define NN   8192
#define SS   1024        // NPOINT
#define KK   32          // NSAMPLE
#define DD   9
#define MCOL (BB*SS*KK)  // 524288 columns
#define NBLK (MCOL/64)   // 8192 gemm blocks

// ---------------- device scratch (static: no cudaMalloc allowed) ----------------
__device__ float  g_X0[(size_t)DD  * MCOL];   // gathered input   (9  x 524288)
__device__ float  g_Y0[(size_t)64  * MCOL];   // layer0 raw out
__device__ float  g_Y1[(size_t)64  * MCOL];   // layer1 raw out
__device__ float  g_Y2[(size_t)128 * MCOL];   // layer2 raw out
__device__ int    g_cent[BB * SS];
__device__ double g_ps [(size_t)128 * NBLK];  // per-block channel sums
__device__ double g_pss[(size_t)128 * NBLK];  // per-block channel sumsq
__device__ float  g_scl[3][128];
__device__ float  g_shf[3][128];

// ---------------- pad kernels: shift ncu capture slot (-s 5 -c 1) onto fps ----------------
__global__ void pad_kernel() {}

// ---------------- FPS: one block per batch, register-resident points ----------------
// distance formula matches XLA/NVPTX fp-contract=fast:
//   d = fma(dz,dz, fma(dy,dy, dx*dx))   (reduce-from-0 fma chain)
__global__ __launch_bounds__(1024) void fps_kernel(const float* __restrict__ xyz)
{
    extern __shared__ float sh[];
    float* sx = sh;
    float* sy = sh + NN;
    float* sz = sh + 2 * NN;
    __shared__ float rv[32];
    __shared__ int   ri[32];
    __shared__ int   s_far;

    int b = blockIdx.x, t = threadIdx.x;
    const float* xb = xyz + (size_t)b * NN * 3;

    float X[8], Y[8], Z[8], Dst[8];
#pragma unroll
    for (int j = 0; j < 8; j++) {
        int p = j * 1024 + t;
        float x = xb[p * 3 + 0];
        float y = xb[p * 3 + 1];
        float z = xb[p * 3 + 2];
        X[j] = x; Y[j] = y; Z[j] = z; Dst[j] = 1e10f;
        sx[p] = x; sy[p] = y; sz[p] = z;   // smem copy only for far-lookup
    }
    if (t == 0) g_cent[b * SS] = 0;
    int far = 0;
    __syncthreads();

    for (int it = 1; it < SS; ++it) {
        float cx = sx[far], cy = sy[far], cz = sz[far];
        float bv = -1.0f; int bi = 0;
#pragma unroll
        for (int j = 0; j < 8; j++) {
            int p = j * 1024 + t;
            float dx = __fsub_rn(X[j], cx);
            float dy = __fsub_rn(Y[j], cy);
            float dz = __fsub_rn(Z[j], cz);
            float d  = fmaf(dz, dz, fmaf(dy, dy, __fmul_rn(dx, dx)));
            float nd = fminf(Dst[j], d);
            Dst[j] = nd;
            if (nd > bv) { bv = nd; bi = p; }   // p increasing -> first-index tie rule
        }
        // warp argmax (tie -> smaller index)
#pragma unroll
        for (int o = 16; o > 0; o >>= 1) {
            float ov = __shfl_down_sync(0xffffffffu, bv, o);
            int   oi = __shfl_down_sync(0xffffffffu, bi, o);
            if (ov > bv || (ov == bv && oi < bi)) { bv = ov; bi = oi; }
        }
        int w = t >> 5, lane = t & 31;
        if (lane == 0) { rv[w] = bv; ri[w] = bi; }
        __syncthreads();
        if (w == 0) {
            bv = rv[lane]; bi = ri[lane];
#pragma unroll
            for (int o = 16; o > 0; o >>= 1) {
                float ov = __shfl_down_sync(0xffffffffu, bv, o);
                int   oi = __shfl_down_sync(0xffffffffu, bi, o);
                if (ov > bv || (ov == bv && oi < bi)) { bv = ov; bi = oi; }
            }
            if (lane == 0) { s_far = bi; g_cent[b * SS + it] = bi; }
        }
        __syncthreads();
        far = s_far;
    }
}

// ---------------- Ball query: warp-per-centroid, register-distributed top-32 ----------------
// The sorted 32-list lives one element per lane (dl,il), ascending by (d, index).
// In-radius pre-filter is exact: self-point has d == 0 <= R2, so every d > R2 slot
// is replaced by first regardless -> output depends only on d <= R2 points.
__global__ __launch_bounds__(256) void ballquery_kernel(const float* __restrict__ xyz,
                                                        const float* __restrict__ points,
                                                        float* __restrict__ out_newxyz)
{
    __shared__ float4 sp[2048];
    int b    = blockIdx.x >> 7;                       // 128 blocks per batch
    int warp = threadIdx.x >> 5;
    int lane = threadIdx.x & 31;
    int s    = ((blockIdx.x & 127) << 3) + warp;      // centroid within batch

    int cidx = g_cent[b * SS + s];
    const float* cp = xyz + ((size_t)b * NN + cidx) * 3;
    float cx = cp[0], cy = cp[1], cz = cp[2];
    float cn2 = fmaf(cz, cz, fmaf(cy, cy, __fmul_rn(cx, cx)));
    if (lane < 3) out_newxyz[(b * SS + s) * 3 + lane] = cp[lane];

    const float R2 = 0.04f;   // float32 of radius**2
    float dl = 3.4e38f;       // rank-`lane` distance (sentinel = empty)
    int   il = 0;

    for (int tile = 0; tile < 4; ++tile) {
        __syncthreads();
        for (int i = threadIdx.x; i < 2048; i += 256) {
            int gp = tile * 2048 + i;
            const float* pp = xyz + ((size_t)b * NN + gp) * 3;
            float px = pp[0], py = pp[1], pz = pp[2];
            sp[i] = make_float4(px, py, pz, fmaf(pz, pz, fmaf(py, py, __fmul_rn(px, px))));
        }
        __syncthreads();
        for (int chunk = 0; chunk < 64; ++chunk) {
            float4 p = sp[chunk * 32 + lane];
            float dot = fmaf(cz, p.z, fmaf(cy, p.y, __fmul_rn(cx, p.x)));
            float d   = __fsub_rn(__fadd_rn(cn2, p.w), __fmul_rn(2.0f, dot));
            float d31 = __shfl_sync(0xffffffffu, dl, 31);
            unsigned mask = __ballot_sync(0xffffffffu, d <= R2 && d < d31);
            while (mask) {
                int c0 = __ffs(mask) - 1;             // ascending lane = ascending index
                mask &= mask - 1;
                float dc = __shfl_sync(0xffffffffu, d, c0);
                d31 = __shfl_sync(0xffffffffu, dl, 31);
                if (dc < d31) {                       // strict <: later equal never displaces
                    int pos = __popc(__ballot_sync(0xffffffffu, dl <= dc)); // after equals -> stable
                    float dprev = __shfl_up_sync(0xffffffffu, dl, 1);
                    int   iprev = __shfl_up_sync(0xffffffffu, il, 1);
                    int ic = tile * 2048 + chunk * 32 + c0;
                    if (lane >= pos) {
                        dl = (lane == pos) ? dc : dprev;
                        il = (lane == pos) ? ic : iprev;
                    }
                }
            }
        }
    }

    // radius replacement + fused gather of the 9 input channels (lane = k slot)
    int first = __shfl_sync(0xffffffffu, il, 0);
    int gi = (dl > R2) ? first : il;
    const float* pr = points + ((size_t)b * NN + gi) * DD;
    int m0 = (b * SS + s) * KK;
    float v[DD];
#pragma unroll
    for (int c = 0; c < DD; c++) v[c] = pr[c];
#pragma unroll
    for (int c = 0; c < DD; c++)
        g_X0[(size_t)c * MCOL + m0 + lane] = v[c];    // coalesced 128B per channel
}

// ---------------- GEMM + bias + deterministic BN partial stats ----------------
// block = 256 threads, tile = COUT rows x 64 cols. thread tile = R rows x 4 cols.
template<int CIN, int COUT, int LAYER>
__global__ __launch_bounds__(256) void gemm_kernel(const float* __restrict__ X,
                                                   float* __restrict__ Y,
                                                   const float* __restrict__ W,
                                                   const float* __restrict__ Bv)
{
    constexpr int R = COUT / 16;
    extern __shared__ float sm[];
    float* WsT  = sm;                    // [CIN][COUT] transposed weights
    float* Xs   = WsT + CIN * COUT;      // [CIN][64]
    float* ssum = Xs  + CIN * 64;        // [COUT]
    float* sss  = ssum + COUT;           // [COUT]

    int t = threadIdx.x;
    int col0 = blockIdx.x * 64;

    for (int i = t; i < CIN * COUT; i += 256) {
        int k = i / COUT, r = i - k * COUT;
        WsT[i] = W[r * CIN + k];
    }
    for (int i = t; i < CIN * 64; i += 256) {
        int c = i >> 6, x = i & 63;
        float v = X[(size_t)c * MCOL + col0 + x];
        if (LAYER > 0) v = fmaxf(fmaf(g_scl[LAYER - 1][c], v, g_shf[LAYER - 1][c]), 0.0f);
        Xs[i] = v;
    }
    __syncthreads();

    int cg = t & 15, rg = t >> 4;
    float acc[R][4];
#pragma unroll
    for (int r = 0; r < R; r++)
#pragma unroll
        for (int c = 0; c < 4; c++) acc[r][c] = 0.0f;

    const float4* Xs4 = reinterpret_cast<const float4*>(Xs);
    const float4* Ws4 = reinterpret_cast<const float4*>(WsT);
#pragma unroll
    for (int k = 0; k < CIN; k++) {
        float4 xv = Xs4[k * 16 + cg];
        float xa[4] = {xv.x, xv.y, xv.z, xv.w};
#pragma unroll
        for (int rr = 0; rr < R; rr += 4) {
            float4 wv = Ws4[k * (COUT / 4) + (rg * R + rr) / 4];
            float wa[4] = {wv.x, wv.y, wv.z, wv.w};
#pragma unroll
            for (int q = 0; q < 4; q++)
#pragma unroll
                for (int cc = 0; cc < 4; cc++)
                    acc[rr + q][cc] = fmaf(wa[q], xa[cc], acc[rr + q][cc]);
        }
    }

    int lane = t & 31;
#pragma unroll
    for (int rr = 0; rr < R; rr++) {
        int r = rg * R + rr;
        float bb = Bv[r];
        float y0 = acc[rr][0] + bb, y1 = acc[rr][1] + bb;
        float y2 = acc[rr][2] + bb, y3 = acc[rr][3] + bb;
        *reinterpret_cast<float4*>(Y + (size_t)r * MCOL + col0 + cg * 4) =
            make_float4(y0, y1, y2, y3);
        float ps = y0 + y1 + y2 + y3;
        float pq = y0*y0 + y1*y1 + y2*y2 + y3*y3;
#pragma unroll
        for (int o = 8; o > 0; o >>= 1) {
            ps += __shfl_xor_sync(0xffffffffu, ps, o);
            pq += __shfl_xor_sync(0xffffffffu, pq, o);
        }
        if ((lane & 15) == 0) { ssum[r] = ps; sss[r] = pq; }  // unique writer per row
    }
    __syncthreads();
    if (t < COUT) {
        g_ps [(size_t)t * NBLK + blockIdx.x] = (double)ssum[t];
        g_pss[(size_t)t * NBLK + blockIdx.x] = (double)sss[t];
    }
}

// ---------------- BN finalize: one block per channel, deterministic tree sum ----------------
__global__ __launch_bounds__(128) void finalize_kernel(const float* __restrict__ gamma,
                                                       const float* __restrict__ beta,
                                                       int layer)
{
    int c = blockIdx.x, t = threadIdx.x;
    __shared__ double sh1[128], sh2[128];
    double a = 0.0, q = 0.0;
    for (int i = t; i < NBLK; i += 128) {
        a += g_ps [(size_t)c * NBLK + i];
        q += g_pss[(size_t)c * NBLK + i];
    }
    sh1[t] = a; sh2[t] = q;
    __syncthreads();
    for (int o = 64; o > 0; o >>= 1) {
        if (t < o) { sh1[t] += sh1[t + o]; sh2[t] += sh2[t + o]; }
        __syncthreads();
    }
    if (t == 0) {
        double n = (double)MCOL;
        double mean = sh1[0] / n;
        double var  = sh2[0] / n - mean * mean;
        float sc = gamma[c] * rsqrtf((float)var + 1e-5f);
        g_scl[layer][c] = sc;
        g_shf[layer][c] = beta[c] - (float)mean * sc;
    }
}

// ---------------- final affine + relu + max over nsample, transposed write ----------------
__global__ __launch_bounds__(256) void maxpool_kernel(float* __restrict__ out)
{
    int g = blockIdx.x * 256 + threadIdx.x;   // (b,s,c) with c fastest
    int c = g & 127;
    int ms = g >> 7;                          // b*1024 + s
    float sc = g_scl[2][c], sh = g_shf[2][c];
    const float4* p = reinterpret_cast<const float4*>(g_Y2 + (size_t)c * MCOL + (size_t)ms * KK);
    float mx = -3.4e38f;
#pragma unroll
    for (int q = 0; q < 8; q++) {
        float4 v = p[q];
        mx = fmaxf(mx, fmaf(sc, v.x, sh));
        mx = fmaxf(mx, fmaf(sc, v.y, sh));
        mx = fmaxf(mx, fmaf(sc, v.z, sh));
        mx = fmaxf(mx, fmaf(sc, v.w, sh));
    }
    out[g] = fmaxf(mx, 0.0f);   // relu commutes with max
}

// ---------------- launch ----------------
extern "C" void kernel_launch(void* const* d_in, const int* in_sizes, int n_in,
                              void* d_out, int out_size)
{
    const float* xyz    = (const float*)d_in[0];
    const float* points = (const float*)d_in[1];
    const float* W0 = (const float*)d_in[2];
    const float* b0 = (const float*)d_in[3];
    const float* g0 = (const float*)d_in[4];
    const float* be0 = (const float*)d_in[5];
    const float* W1 = (const float*)d_in[6];
    const float* b1 = (const float*)d_in[7];
    const float* g1 = (const float*)d_in[8];
    const float* be1 = (const float*)d_in[9];
    const float* W2 = (const float*)d_in[10];
    const float* b2 = (const float*)d_in[11];
    const float* g2 = (const float*)d_in[12];
    const float* be2 = (const float*)d_in[13];

    float* out      = (float*)d_out;
    float* out_feat = out + BB * SS * 3;

    float *pX0, *pY0, *pY1, *pY2;
    cudaGetSymbolAddress((void**)&pX0, g_X0);
    cudaGetSymbolAddress((void**)&pY0, g_Y0);
    cudaGetSymbolAddress((void**)&pY1, g_Y1);
    cudaGetSymbolAddress((void**)&pY2, g_Y2);

    // 5 pad launches so ncu (-s 5 -c 1) captures fps_kernel
    for (int i = 0; i < 5; i++) pad_kernel<<<1, 32>>>();

    // FPS (96KB dynamic smem)
    cudaFuncSetAttribute(fps_kernel, cudaFuncAttributeMaxDynamicSharedMemorySize, 3 * NN * 4);
    fps_kernel<<<BB, 1024, 3 * NN * 4>>>(xyz);

    // ball query + gather + new_xyz output (warp per centroid)
    ballquery_kernel<<<BB * 128, 256>>>(xyz, points, out);

    // layer 0: 9 -> 64
    {
        size_t smem = (size_t)(9 * 64 + 9 * 64 + 2 * 64) * 4;
        cudaFuncSetAttribute(gemm_kernel<9, 64, 0>, cudaFuncAttributeMaxDynamicSharedMemorySize, (int)smem);
        gemm_kernel<9, 64, 0><<<NBLK, 256, smem>>>(pX0, pY0, W0, b0);
        finalize_kernel<<<64, 128>>>(g0, be0, 0);
    }
    // layer 1: 64 -> 64 (applies BN0+relu on input)
    {
        size_t smem = (size_t)(64 * 64 + 64 * 64 + 2 * 64) * 4;
        cudaFuncSetAttribute(gemm_kernel<64, 64, 1>, cudaFuncAttributeMaxDynamicSharedMemorySize, (int)smem);
        gemm_kernel<64, 64, 1><<<NBLK, 256, smem>>>(pY0, pY1, W1, b1);
        finalize_kernel<<<64, 128>>>(g1, be1, 1);
    }
    // layer 2: 64 -> 128 (applies BN1+relu on input)
    {
        size_t smem = (size_t)(64 * 128 + 64 * 64 + 2 * 128) * 4;
        cudaFuncSetAttribute(gemm_kernel<64, 128, 2>, cudaFuncAttributeMaxDynamicSharedMemorySize, (int)smem);
        gemm_kernel<64, 128, 2><<<NBLK, 256, smem>>>(pY1, pY2, W2, b2);
        finalize_kernel<<<128, 128>>>(g2, be2, 2);
    }
    // BN2 + relu + max over nsample -> transposed feature output
    maxpool_kernel<<<(BB * SS * 128) / 256, 256>>>(out_feat);
}

// round 5
// speedup vs baseline: 16.2236x; 1.5076x over previous
#include <cuda_runtime.h>
#include <cstddef>

#define BB   16
#define NN   8192
#define SS   1024        // NPOINT
#define KK   32          // NSAMPLE
#define DD   9
#define MCOL (BB*SS*KK)  // 524288 columns
#define NBLK (MCOL/128)  // 4096 gemm blocks (128-wide tiles)

// ---------------- device scratch (static: no cudaMalloc allowed) ----------------
__device__ float  g_X0[(size_t)DD  * MCOL];   // gathered input   (9  x 524288)
__device__ float  g_Y0[(size_t)64  * MCOL];   // layer0 raw out
__device__ float  g_Y1[(size_t)64  * MCOL];   // layer1 raw out
__device__ float  g_P2[(size_t)BB * SS * 128];// layer2 pooled raw max  [ms][c]
__device__ int    g_cent[BB * SS];
__device__ double g_ps [(size_t)128 * NBLK];  // per-block channel sums
__device__ double g_pss[(size_t)128 * NBLK];  // per-block channel sumsq
__device__ float  g_scl[3][128];
__device__ float  g_shf[3][128];

// ---------------- f32x2 packed helpers (sm_100+) ----------------
__device__ __forceinline__ unsigned long long pack2(float a, float b) {
    unsigned long long r;
    asm("mov.b64 %0, {%1, %2};" : "=l"(r) : "f"(a), "f"(b));
    return r;
}
__device__ __forceinline__ void unpack2(unsigned long long v, float& a, float& b) {
    asm("mov.b64 {%0, %1}, %2;" : "=f"(a), "=f"(b) : "l"(v));
}
__device__ __forceinline__ unsigned long long add2(unsigned long long a, unsigned long long b) {
    unsigned long long r;
    asm("add.rn.f32x2 %0, %1, %2;" : "=l"(r) : "l"(a), "l"(b));
    return r;
}
__device__ __forceinline__ unsigned long long mul2(unsigned long long a, unsigned long long b) {
    unsigned long long r;
    asm("mul.rn.f32x2 %0, %1, %2;" : "=l"(r) : "l"(a), "l"(b));
    return r;
}
__device__ __forceinline__ unsigned long long fma2(unsigned long long a, unsigned long long b, unsigned long long c) {
    unsigned long long r;
    asm("fma.rn.f32x2 %0, %1, %2, %3;" : "=l"(r) : "l"(a), "l"(b), "l"(c));
    return r;
}

// ---------------- pad kernels: shift ncu capture slot onto fps/ballquery ----------------
__global__ void pad_kernel() {}

// ---------------- FPS: one block per batch, f32x2 math + REDUX argmax ----------------
// d = fma(dz,dz, fma(dy,dy, dx*dx)) with dx = x + (-cx)  (== x - cx exactly)
__global__ __launch_bounds__(1024) void fps_kernel(const float* __restrict__ xyz)
{
    extern __shared__ float sh[];
    float* sx = sh;
    float* sy = sh + NN;
    float* sz = sh + 2 * NN;
    __shared__ unsigned bufv[2][32];
    __shared__ unsigned bufi[2][32];

    int b = blockIdx.x, t = threadIdx.x;
    int lane = t & 31, w = t >> 5;
    const float* xb = xyz + (size_t)b * NN * 3;

    float xs[8], ys[8], zs[8], Dst[8];
#pragma unroll
    for (int j = 0; j < 8; j++) {
        int p = j * 1024 + t;
        xs[j] = xb[p * 3 + 0];
        ys[j] = xb[p * 3 + 1];
        zs[j] = xb[p * 3 + 2];
        Dst[j] = 1e10f;
        sx[p] = xs[j]; sy[p] = ys[j]; sz[p] = zs[j];
    }
    unsigned long long X2[4], Y2[4], Z2[4];
#pragma unroll
    for (int jp = 0; jp < 4; jp++) {
        X2[jp] = pack2(xs[2 * jp], xs[2 * jp + 1]);
        Y2[jp] = pack2(ys[2 * jp], ys[2 * jp + 1]);
        Z2[jp] = pack2(zs[2 * jp], zs[2 * jp + 1]);
    }
    if (t == 0) g_cent[b * SS] = 0;
    int far = 0, par = 0;
    __syncthreads();

    for (int it = 1; it < SS; ++it) {
        float cx = sx[far], cy = sy[far], cz = sz[far];
        unsigned long long cx2 = pack2(-cx, -cx);
        unsigned long long cy2 = pack2(-cy, -cy);
        unsigned long long cz2 = pack2(-cz, -cz);
        float bv = -1.0f; int bi = 0;
#pragma unroll
        for (int jp = 0; jp < 4; jp++) {
            unsigned long long dx2 = add2(X2[jp], cx2);
            unsigned long long dy2 = add2(Y2[jp], cy2);
            unsigned long long dz2 = add2(Z2[jp], cz2);
            unsigned long long d2 = fma2(dz2, dz2, fma2(dy2, dy2, mul2(dx2, dx2)));
            float dlo, dhi;
            unpack2(d2, dlo, dhi);
            float nlo = fminf(Dst[2 * jp], dlo);
            float nhi = fminf(Dst[2 * jp + 1], dhi);
            Dst[2 * jp] = nlo;
            Dst[2 * jp + 1] = nhi;
            if (nlo > bv) { bv = nlo; bi = 2 * jp * 1024 + t; }       // ascending p
            if (nhi > bv) { bv = nhi; bi = (2 * jp + 1) * 1024 + t; } // strict > keeps first
        }
        // warp argmax via REDUX (d >= 0 so float bits are order-preserving)
        unsigned vb = __float_as_uint(bv);
        unsigned m1 = __reduce_max_sync(0xffffffffu, vb);
        unsigned c1 = (vb == m1) ? (unsigned)bi : 0xffffffffu;
        unsigned i1 = __reduce_min_sync(0xffffffffu, c1);
        if (lane == 0) { bufv[par][w] = m1; bufi[par][w] = i1; }
        __syncthreads();
        // every warp does the 32-warp final reduce itself (no 2nd barrier)
        unsigned v2 = bufv[par][lane];
        unsigned i2 = bufi[par][lane];
        unsigned m2 = __reduce_max_sync(0xffffffffu, v2);
        unsigned c2 = (v2 == m2) ? i2 : 0xffffffffu;
        far = (int)__reduce_min_sync(0xffffffffu, c2);
        if (t == 0) g_cent[b * SS + it] = far;
        par ^= 1;
    }
}

// ---------------- Ball query: warp-per-centroid, register-distributed top-32 ----------------
__global__ __launch_bounds__(256) void ballquery_kernel(const float* __restrict__ xyz,
                                                        const float* __restrict__ points,
                                                        float* __restrict__ out_newxyz)
{
    __shared__ float4 sp[2048];
    int b    = blockIdx.x >> 7;                       // 128 blocks per batch
    int warp = threadIdx.x >> 5;
    int lane = threadIdx.x & 31;
    int s    = ((blockIdx.x & 127) << 3) + warp;      // centroid within batch

    int cidx = g_cent[b * SS + s];
    const float* cp = xyz + ((size_t)b * NN + cidx) * 3;
    float cx = cp[0], cy = cp[1], cz = cp[2];
    float cn2 = fmaf(cz, cz, fmaf(cy, cy, __fmul_rn(cx, cx)));
    if (lane < 3) out_newxyz[(b * SS + s) * 3 + lane] = cp[lane];

    const float R2 = 0.04f;   // float32 of radius**2
    float dl = 3.4e38f;       // rank-`lane` distance (sentinel = empty)
    int   il = 0;

    for (int tile = 0; tile < 4; ++tile) {
        __syncthreads();
        for (int i = threadIdx.x; i < 2048; i += 256) {
            int gp = tile * 2048 + i;
            const float* pp = xyz + ((size_t)b * NN + gp) * 3;
            float px = pp[0], py = pp[1], pz = pp[2];
            sp[i] = make_float4(px, py, pz, fmaf(pz, pz, fmaf(py, py, __fmul_rn(px, px))));
        }
        __syncthreads();
        for (int chunk = 0; chunk < 64; ++chunk) {
            float4 p = sp[chunk * 32 + lane];
            float dot = fmaf(cz, p.z, fmaf(cy, p.y, __fmul_rn(cx, p.x)));
            float d   = __fsub_rn(__fadd_rn(cn2, p.w), __fmul_rn(2.0f, dot));
            float d31 = __shfl_sync(0xffffffffu, dl, 31);
            unsigned mask = __ballot_sync(0xffffffffu, d <= R2 && d < d31);
            while (mask) {
                int c0 = __ffs(mask) - 1;             // ascending lane = ascending index
                mask &= mask - 1;
                float dc = __shfl_sync(0xffffffffu, d, c0);
                d31 = __shfl_sync(0xffffffffu, dl, 31);
                if (dc < d31) {                       // strict <: later equal never displaces
                    int pos = __popc(__ballot_sync(0xffffffffu, dl <= dc)); // after equals -> stable
                    float dprev = __shfl_up_sync(0xffffffffu, dl, 1);
                    int   iprev = __shfl_up_sync(0xffffffffu, il, 1);
                    int ic = tile * 2048 + chunk * 32 + c0;
                    if (lane >= pos) {
                        dl = (lane == pos) ? dc : dprev;
                        il = (lane == pos) ? ic : iprev;
                    }
                }
            }
        }
    }

    // radius replacement + fused gather of the 9 input channels (lane = k slot)
    int first = __shfl_sync(0xffffffffu, il, 0);
    int gi = (dl > R2) ? first : il;
    const float* pr = points + ((size_t)b * NN + gi) * DD;
    int m0 = (b * SS + s) * KK;
    float v[DD];
#pragma unroll
    for (int c = 0; c < DD; c++) v[c] = pr[c];
#pragma unroll
    for (int c = 0; c < DD; c++)
        g_X0[(size_t)c * MCOL + m0 + lane] = v[c];    // coalesced 128B per channel
}

// ---------------- GEMM (FFMA2) + bias + BN partials; POOL fuses maxpool ----------------
// 256 threads, tile = COUT rows x 128 cols. thread = R rows x 8 cols (4 f32x2 accs/row).
template<int CIN, int COUT, int LAYER, bool POOL>
__global__ __launch_bounds__(256) void gemm_kernel(const float* __restrict__ X,
                                                   float* __restrict__ Y,
                                                   const float* __restrict__ W,
                                                   const float* __restrict__ Bv)
{
    constexpr int R = COUT / 16;
    extern __shared__ float sm[];
    float* WsT  = sm;                    // [CIN][COUT] transposed weights
    float* Xs   = WsT + CIN * COUT;      // [CIN][128]
    float* ssum = Xs  + CIN * 128;       // [COUT]
    float* sss  = ssum + COUT;           // [COUT]

    int t = threadIdx.x;
    size_t col0 = (size_t)blockIdx.x * 128;

    for (int i = t; i < CIN * COUT; i += 256) {
        int k = i / COUT, r = i - k * COUT;
        WsT[i] = W[r * CIN + k];
    }
    for (int i = t; i < CIN * 128; i += 256) {
        int c = i >> 7, x = i & 127;
        float v = X[(size_t)c * MCOL + col0 + x];
        if (LAYER > 0) v = fmaxf(fmaf(g_scl[LAYER - 1][c], v, g_shf[LAYER - 1][c]), 0.0f);
        Xs[i] = v;
    }
    __syncthreads();

    int cg = t & 15, rg = t >> 4;
    unsigned long long acc[R][4];
#pragma unroll
    for (int r = 0; r < R; r++)
#pragma unroll
        for (int c = 0; c < 4; c++) acc[r][c] = 0ull;

    const ulonglong2* Xs2 = reinterpret_cast<const ulonglong2*>(Xs);
#pragma unroll
    for (int k = 0; k < CIN; k++) {
        ulonglong2 xa = Xs2[k * 32 + cg * 2];
        ulonglong2 xb = Xs2[k * 32 + cg * 2 + 1];
        unsigned long long xs4[4] = {xa.x, xa.y, xb.x, xb.y};
        const float4* Wr = reinterpret_cast<const float4*>(WsT + k * COUT + rg * R);
#pragma unroll
        for (int rr4 = 0; rr4 < R; rr4 += 4) {
            float4 wv = Wr[rr4 / 4];
            float wa[4] = {wv.x, wv.y, wv.z, wv.w};
#pragma unroll
            for (int q = 0; q < 4; q++) {
                unsigned long long w2 = pack2(wa[q], wa[q]);
#pragma unroll
                for (int c = 0; c < 4; c++)
                    acc[rr4 + q][c] = fma2(w2, xs4[c], acc[rr4 + q][c]);
            }
        }
    }

    int lane = t & 31;
#pragma unroll
    for (int rr = 0; rr < R; rr++) {
        int r = rg * R + rr;
        float bb = Bv[r];
        float y[8];
#pragma unroll
        for (int c = 0; c < 4; c++) {
            float a, b2;
            unpack2(acc[rr][c], a, b2);
            y[2 * c]     = a + bb;
            y[2 * c + 1] = b2 + bb;
        }
        if (!POOL) {
            *reinterpret_cast<float4*>(Y + (size_t)r * MCOL + col0 + cg * 8) =
                make_float4(y[0], y[1], y[2], y[3]);
            *reinterpret_cast<float4*>(Y + (size_t)r * MCOL + col0 + cg * 8 + 4) =
                make_float4(y[4], y[5], y[6], y[7]);
        } else {
            // raw-y max over this thread's 8 cols, then over the 4 cg-threads of the
            // 32-col group (affine with scale>0 and relu commute with max exactly)
            float pm = y[0];
#pragma unroll
            for (int c = 1; c < 8; c++) pm = fmaxf(pm, y[c]);
            pm = fmaxf(pm, __shfl_xor_sync(0xffffffffu, pm, 1));
            pm = fmaxf(pm, __shfl_xor_sync(0xffffffffu, pm, 2));
            if ((cg & 3) == 0)
                g_P2[((size_t)blockIdx.x * 4 + (cg >> 2)) * 128 + r] = pm;
        }
        float ps = ((y[0] + y[1]) + (y[2] + y[3])) + ((y[4] + y[5]) + (y[6] + y[7]));
        float pq = ((y[0]*y[0] + y[1]*y[1]) + (y[2]*y[2] + y[3]*y[3]))
                 + ((y[4]*y[4] + y[5]*y[5]) + (y[6]*y[6] + y[7]*y[7]));
#pragma unroll
        for (int o = 8; o > 0; o >>= 1) {
            ps += __shfl_xor_sync(0xffffffffu, ps, o);
            pq += __shfl_xor_sync(0xffffffffu, pq, o);
        }
        if ((lane & 15) == 0) { ssum[r] = ps; sss[r] = pq; }
    }
    __syncthreads();
    if (t < COUT) {
        g_ps [(size_t)t * NBLK + blockIdx.x] = (double)ssum[t];
        g_pss[(size_t)t * NBLK + blockIdx.x] = (double)sss[t];
    }
}

// ---------------- BN finalize: one block per channel, deterministic tree sum ----------------
__global__ __launch_bounds__(128) void finalize_kernel(const float* __restrict__ gamma,
                                                       const float* __restrict__ beta,
                                                       int layer)
{
    int c = blockIdx.x, t = threadIdx.x;
    __shared__ double sh1[128], sh2[128];
    double a = 0.0, q = 0.0;
    for (int i = t; i < NBLK; i += 128) {
        a += g_ps [(size_t)c * NBLK + i];
        q += g_pss[(size_t)c * NBLK + i];
    }
    sh1[t] = a; sh2[t] = q;
    __syncthreads();
    for (int o = 64; o > 0; o >>= 1) {
        if (t < o) { sh1[t] += sh1[t + o]; sh2[t] += sh2[t + o]; }
        __syncthreads();
    }
    if (t == 0) {
        double n = (double)MCOL;
        double mean = sh1[0] / n;
        double var  = sh2[0] / n - mean * mean;
        float sc = gamma[c] * rsqrtf((float)var + 1e-5f);
        g_scl[layer][c] = sc;
        g_shf[layer][c] = beta[c] - (float)mean * sc;
    }
}

// ---------------- final: BN2 affine + relu on pooled values (already [ms][c]) ----------------
__global__ __launch_bounds__(256) void final_kernel(float* __restrict__ out)
{
    int g = blockIdx.x * 256 + threadIdx.x;
    int c = g & 127;
    out[g] = fmaxf(fmaf(g_scl[2][c], g_P2[g], g_shf[2][c]), 0.0f);
}

// ---------------- launch ----------------
extern "C" void kernel_launch(void* const* d_in, const int* in_sizes, int n_in,
                              void* d_out, int out_size)
{
    const float* xyz    = (const float*)d_in[0];
    const float* points = (const float*)d_in[1];
    const float* W0 = (const float*)d_in[2];
    const float* b0 = (const float*)d_in[3];
    const float* g0 = (const float*)d_in[4];
    const float* be0 = (const float*)d_in[5];
    const float* W1 = (const float*)d_in[6];
    const float* b1 = (const float*)d_in[7];
    const float* g1 = (const float*)d_in[8];
    const float* be1 = (const float*)d_in[9];
    const float* W2 = (const float*)d_in[10];
    const float* b2 = (const float*)d_in[11];
    const float* g2 = (const float*)d_in[12];
    const float* be2 = (const float*)d_in[13];

    float* out      = (float*)d_out;
    float* out_feat = out + BB * SS * 3;

    float *pX0, *pY0, *pY1;
    cudaGetSymbolAddress((void**)&pX0, g_X0);
    cudaGetSymbolAddress((void**)&pY0, g_Y0);
    cudaGetSymbolAddress((void**)&pY1, g_Y1);

    // 3 pads: ncu capture slot (1-based ~#4-5) lands on fps or ballquery
    for (int i = 0; i < 3; i++) pad_kernel<<<1, 32>>>();

    // FPS (96KB dynamic smem)
    cudaFuncSetAttribute(fps_kernel, cudaFuncAttributeMaxDynamicSharedMemorySize, 3 * NN * 4);
    fps_kernel<<<BB, 1024, 3 * NN * 4>>>(xyz);

    // ball query + gather + new_xyz output (warp per centroid)
    ballquery_kernel<<<BB * 128, 256>>>(xyz, points, out);

    // layer 0: 9 -> 64
    {
        size_t smem = (size_t)(9 * 64 + 9 * 128 + 2 * 64) * 4;
        cudaFuncSetAttribute(gemm_kernel<9, 64, 0, false>, cudaFuncAttributeMaxDynamicSharedMemorySize, (int)smem);
        gemm_kernel<9, 64, 0, false><<<NBLK, 256, smem>>>(pX0, pY0, W0, b0);
        finalize_kernel<<<64, 128>>>(g0, be0, 0);
    }
    // layer 1: 64 -> 64 (applies BN0+relu on input)
    {
        size_t smem = (size_t)(64 * 64 + 64 * 128 + 2 * 64) * 4;
        cudaFuncSetAttribute(gemm_kernel<64, 64, 1, false>, cudaFuncAttributeMaxDynamicSharedMemorySize, (int)smem);
        gemm_kernel<64, 64, 1, false><<<NBLK, 256, smem>>>(pY0, pY1, W1, b1);
        finalize_kernel<<<64, 128>>>(g1, be1, 1);
    }
    // layer 2: 64 -> 128, maxpool fused (no Y2 materialization)
    {
        size_t smem = (size_t)(64 * 128 + 64 * 128 + 2 * 128) * 4;
        cudaFuncSetAttribute(gemm_kernel<64, 128, 2, true>, cudaFuncAttributeMaxDynamicSharedMemorySize, (int)smem);
        gemm_kernel<64, 128, 2, true><<<NBLK, 256, smem>>>(pY1, pY0 /*unused*/, W2, b2);
        finalize_kernel<<<128, 128>>>(g2, be2, 2);
    }
    // BN2 affine + relu on pooled values -> feature output
    final_kernel<<<(BB * SS * 128) / 256, 256>>>(out_feat);
}